// round 8
// baseline (speedup 1.0000x reference)
#include <cuda_runtime.h>

#define TT 512
#define BTILE 16
#define NTHREADS 1024

typedef unsigned long long ull;

struct Smem {
    float w0[64 * 256];    // [k][j*4+gate] <- w_hh0[(gate*64+j)*64+k]
    float wi1[64 * 256];   // same regroup of w_ih1
    float wh1[64 * 256];   // same regroup of w_hh1
    float hA[2][64 * 16];  // layer-0 hidden, [buf][k*16 + b]
    float hB[2][64 * 16];  // layer-1 hidden
    float xs[2][BTILE * 4];
};

__device__ __forceinline__ ull pack2(float x, float y) {
    ull r;
    asm("mov.b64 %0, {%1, %2};" : "=l"(r) : "f"(x), "f"(y));
    return r;
}
__device__ __forceinline__ void unpack2(ull v, float& x, float& y) {
    asm("mov.b64 {%0, %1}, %2;" : "=f"(x), "=f"(y) : "l"(v));
}
__device__ __forceinline__ ull fma2(ull a, ull b, ull c) {
    ull d;
    asm("fma.rn.f32x2 %0, %1, %2, %3;" : "=l"(d) : "l"(a), "l"(b), "l"(c));
    return d;
}
__device__ __forceinline__ float tanh_ap(float x) {
    float y;
    asm("tanh.approx.f32 %0, %1;" : "=f"(y) : "f"(x));
    return y;
}
__device__ __forceinline__ float sig_ap(float x) {
    return fmaf(tanh_ap(x * 0.5f), 0.5f, 0.5f);
}

// acc[g]: gate g for batch rows (2p, 2p+1). Two cells; c in regs.
__device__ __forceinline__ void cell2(const ull acc[4], float c[2], float hn[2]) {
    float i0, i1, f0, f1, g0, g1, o0, o1;
    unpack2(acc[0], i0, i1);
    unpack2(acc[1], f0, f1);
    unpack2(acc[2], g0, g1);
    unpack2(acc[3], o0, o1);
    float I0 = sig_ap(i0), F0 = sig_ap(f0), G0 = tanh_ap(g0), O0 = sig_ap(o0);
    c[0] = F0 * c[0] + I0 * G0;
    hn[0] = O0 * tanh_ap(c[0]);
    float I1 = sig_ap(i1), F1 = sig_ap(f1), G1 = tanh_ap(g1), O1 = sig_ap(o1);
    c[1] = F1 * c[1] + I1 * G1;
    hn[1] = O1 * tanh_ap(c[1]);
}

// K=64 matvec: h = 8B/lane (4 distinct pairs -> broadcast, 1 wf),
// w = float4 shared by 4 lanes (8 distinct -> 1 wf).
__device__ __forceinline__ void matvec64(const float* __restrict__ hr,
                                         const float* __restrict__ wp,
                                         ull acc[4]) {
#pragma unroll 8
    for (int k = 0; k < 64; k++) {
        ull hp = *(const ull*)(hr + k * 16);
        float4 w = *(const float4*)(wp + (k << 8));
        acc[0] = fma2(hp, pack2(w.x, w.x), acc[0]);
        acc[1] = fma2(hp, pack2(w.y, w.y), acc[1]);
        acc[2] = fma2(hp, pack2(w.z, w.z), acc[2]);
        acc[3] = fma2(hp, pack2(w.w, w.w), acc[3]);
    }
}

// fused dual matvec for layer 1: both W_ih1*h0 and W_hh1*h1 into acc
__device__ __forceinline__ void matvec64x2(const float* __restrict__ ha,
                                           const float* __restrict__ hb,
                                           const float* __restrict__ wia,
                                           const float* __restrict__ wib,
                                           ull acc[4]) {
#pragma unroll 8
    for (int k = 0; k < 64; k++) {
        ull hp0 = *(const ull*)(ha + k * 16);
        float4 wa = *(const float4*)(wia + (k << 8));
        acc[0] = fma2(hp0, pack2(wa.x, wa.x), acc[0]);
        acc[1] = fma2(hp0, pack2(wa.y, wa.y), acc[1]);
        acc[2] = fma2(hp0, pack2(wa.z, wa.z), acc[2]);
        acc[3] = fma2(hp0, pack2(wa.w, wa.w), acc[3]);
        ull hp1 = *(const ull*)(hb + k * 16);
        float4 wb = *(const float4*)(wib + (k << 8));
        acc[0] = fma2(hp1, pack2(wb.x, wb.x), acc[0]);
        acc[1] = fma2(hp1, pack2(wb.y, wb.y), acc[1]);
        acc[2] = fma2(hp1, pack2(wb.z, wb.z), acc[2]);
        acc[3] = fma2(hp1, pack2(wb.w, wb.w), acc[3]);
    }
}

__global__ void __launch_bounds__(NTHREADS, 1)
lstm_fused_kernel(const float* __restrict__ x,
                  const float* __restrict__ w_ih0, const float* __restrict__ w_hh0,
                  const float* __restrict__ b_ih0, const float* __restrict__ b_hh0,
                  const float* __restrict__ w_ih1, const float* __restrict__ w_hh1,
                  const float* __restrict__ b_ih1, const float* __restrict__ b_hh1,
                  const float* __restrict__ fc_w, const float* __restrict__ fc_b,
                  float* __restrict__ out)
{
    extern __shared__ __align__(16) unsigned char smem_raw[];
    Smem& sh = *reinterpret_cast<Smem*>(smem_raw);
    const int tid = threadIdx.x;
    const int b0 = blockIdx.x * BTILE;

    // ---- stage recurrent weights, regrouped: [k][j*4+gate] ----
    for (int e = tid; e < 64 * 256; e += NTHREADS) {
        int row = e >> 6, k = e & 63;
        int gate = row >> 6, jj = row & 63;
        int d = k * 256 + jj * 4 + gate;
        sh.w0[d] = w_hh0[e];
        sh.wi1[d] = w_ih1[e];
        sh.wh1[d] = w_hh1[e];
    }
    // ---- zero h buffers ----
    for (int e = tid; e < 1024; e += NTHREADS) {
        sh.hA[0][e] = 0.f; sh.hA[1][e] = 0.f;
        sh.hB[0][e] = 0.f; sh.hB[1][e] = 0.f;
    }
    // ---- preload x for t=0 ----
    if (tid < BTILE)
        *(float4*)&sh.xs[0][tid * 4] = ((const float4*)x)[(size_t)(b0 + tid) * TT];

    const int wid = tid >> 5;
    const int lane = tid & 31;
    const bool isGa = (wid < 16);          // Ga: layer 0; Gbc: layer 1
    const int lw = wid & 15;               // warp within group (0..15)
    const int j = (lw & 7) * 8 + (lane >> 2);          // hidden unit 0..63
    const int pr = (lw >> 3) * 4 + (lane & 3);         // row-pair 0..7
    const int pr2 = pr * 2;

    float wi0[16], bias0[4];
    ull bias1[4] = {0, 0, 0, 0};
    if (isGa) {
#pragma unroll
        for (int g = 0; g < 4; g++) {
            float4 wv = *(const float4*)(w_ih0 + (g * 64 + j) * 4);
            wi0[g * 4 + 0] = wv.x; wi0[g * 4 + 1] = wv.y;
            wi0[g * 4 + 2] = wv.z; wi0[g * 4 + 3] = wv.w;
            bias0[g] = b_ih0[g * 64 + j] + b_hh0[g * 64 + j];
        }
    } else {
#pragma unroll
        for (int g = 0; g < 4; g++) {
            float bb = b_ih1[g * 64 + j] + b_hh1[g * 64 + j];
            bias1[g] = pack2(bb, bb);
        }
    }
    float c[2] = {0.f, 0.f};

    __syncthreads();

    // ============ pipelined recurrence ============
    // round r: Ga: layer-0 t=r (r<512); Gbc: layer-1 t=r-1 (r>=1)
    for (int r = 0; r <= TT; r++) {
        float4 xpre;
        const bool pre = (tid < BTILE) && (r <= TT - 2);
        if (pre) xpre = ((const float4*)x)[(size_t)(b0 + tid) * TT + (r + 1)];

        if (isGa) {
            if (r < TT) {
                ull acc[4];
                const float4* xp = (const float4*)sh.xs[r & 1];
                float4 xa = xp[pr2];
                float4 xb = xp[pr2 + 1];
#pragma unroll
                for (int g = 0; g < 4; g++) {
                    float s0 = bias0[g] + wi0[g*4]*xa.x + wi0[g*4+1]*xa.y
                                        + wi0[g*4+2]*xa.z + wi0[g*4+3]*xa.w;
                    float s1 = bias0[g] + wi0[g*4]*xb.x + wi0[g*4+1]*xb.y
                                        + wi0[g*4+2]*xb.z + wi0[g*4+3]*xb.w;
                    acc[g] = pack2(s0, s1);
                }
                matvec64(sh.hA[r & 1] + pr2, sh.w0 + j * 4, acc);
                float hn[2];
                cell2(acc, c, hn);
                *(ull*)(sh.hA[(r + 1) & 1] + j * 16 + pr2) = pack2(hn[0], hn[1]);
            }
        } else {
            if (r >= 1) {
                ull acc[4];
#pragma unroll
                for (int g = 0; g < 4; g++) acc[g] = bias1[g];
                matvec64x2(sh.hA[r & 1] + pr2, sh.hB[r & 1] + pr2,
                           sh.wi1 + j * 4, sh.wh1 + j * 4, acc);
                float hn[2];
                cell2(acc, c, hn);
                *(ull*)(sh.hB[(r + 1) & 1] + j * 16 + pr2) = pack2(hn[0], hn[1]);
            }
        }

        if (pre) *(float4*)&sh.xs[(r + 1) & 1][tid * 4] = xpre;
        __syncthreads();
    }

    // ============ FC + tanh epilogue ============
    // h_n (layer 1, t=511) finalized in round 512 -> hB[1].
    for (int e = tid; e < 4096; e += NTHREADS) {
        int jj = e >> 6, k = e & 63;
        sh.w0[k * 64 + jj] = fc_w[e]; // transpose: [k][j]
    }
    __syncthreads();

    {
        const int q = tid >> 6;   // batch row 0..15
        const int jo = tid & 63;  // output unit
        const float* hfin = sh.hB[1];
        float acc = fc_b[jo];
#pragma unroll 8
        for (int k = 0; k < 64; k++)
            acc += sh.w0[k * 64 + jo] * hfin[k * 16 + q];
        out[(size_t)(b0 + q) * 64 + jo] = tanh_ap(acc);
    }
}

extern "C" void kernel_launch(void* const* d_in, const int* in_sizes, int n_in,
                              void* d_out, int out_size) {
    const float* x     = (const float*)d_in[0];
    const float* w_ih0 = (const float*)d_in[1];
    const float* w_hh0 = (const float*)d_in[2];
    const float* b_ih0 = (const float*)d_in[3];
    const float* b_hh0 = (const float*)d_in[4];
    const float* w_ih1 = (const float*)d_in[5];
    const float* w_hh1 = (const float*)d_in[6];
    const float* b_ih1 = (const float*)d_in[7];
    const float* b_hh1 = (const float*)d_in[8];
    const float* fc_w  = (const float*)d_in[9];
    const float* fc_b  = (const float*)d_in[10];
    float* out = (float*)d_out;

    const int smem = (int)sizeof(Smem);
    cudaFuncSetAttribute(lstm_fused_kernel,
                         cudaFuncAttributeMaxDynamicSharedMemorySize, smem);
    lstm_fused_kernel<<<2048 / BTILE, NTHREADS, smem>>>(
        x, w_ih0, w_hh0, b_ih0, b_hh0,
        w_ih1, w_hh1, b_ih1, b_hh1, fc_w, fc_b, out);
}